// round 15
// baseline (speedup 1.0000x reference)
#include <cuda_runtime.h>
#include <cuda_fp16.h>
#include <math.h>
#include <stdint.h>

// Problem constants
constexpr int B_ = 4;
constexpr int T_ = 2048;
constexpr int D_ = 1024;
constexpr int H_ = 16;
constexpr int DK_ = 64;
constexpr int M_ = B_ * T_;   // 8192
constexpr int N_ = D_;        // 1024
constexpr int K_ = D_;        // 1024

// fp16 arenas.
constexpr size_t XOFF = 0;
constexpr size_t AOFF = (size_t)M_ * K_;
constexpr size_t AF_SZ = AOFF + (size_t)M_ * D_;
__device__ __half g_af[AF_SZ];
__device__ __half g_wh[4ull * N_ * K_];

// Q/K/V single fp16, layout [B*H, T, DK]
constexpr size_t QKV_SZ = (size_t)B_ * H_ * T_ * DK_;
__device__ __half g_qf[QKV_SZ];
__device__ __half g_kf[QKV_SZ];
__device__ __half g_vf[QKV_SZ];

// ---------------------------------------------------------------------------
// Fused converter: x and W0..W3 -> single fp16
// ---------------------------------------------------------------------------
constexpr int NBX = (M_ * K_ / 8) / 256;   // 4096
constexpr int NBW = (N_ * K_ / 8) / 256;   // 512

__global__ void conv_all(const float* __restrict__ x,
                         const float* __restrict__ w0, const float* __restrict__ w1,
                         const float* __restrict__ w2, const float* __restrict__ w3)
{
    const int blk = blockIdx.x;
    const float* src;
    __half* dst;
    int i;
    if (blk < NBX) {
        src = x; dst = g_af;
        i = blk * 256 + threadIdx.x;
    } else {
        const int r = blk - NBX;
        const int w = r / NBW;
        src = (w == 0) ? w0 : (w == 1) ? w1 : (w == 2) ? w2 : w3;
        dst = g_wh + (size_t)w * N_ * K_;
        i = (r % NBW) * 256 + threadIdx.x;
    }
    const float4* p4 = (const float4*)src;
    float4 a = p4[2 * i], b = p4[2 * i + 1];
    __half2 h[4];
    h[0] = __floats2half2_rn(a.x, a.y);
    h[1] = __floats2half2_rn(a.z, a.w);
    h[2] = __floats2half2_rn(b.x, b.y);
    h[3] = __floats2half2_rn(b.z, b.w);
    *(uint4*)(dst + (size_t)i * 8) = *(uint4*)h;
}

// ---------------------------------------------------------------------------
// MMA helpers
// ---------------------------------------------------------------------------
__device__ __forceinline__ void cp16(uint32_t dst, const void* src)
{
    asm volatile("cp.async.cg.shared.global [%0],[%1],16;\n" :: "r"(dst), "l"(src));
}
__device__ __forceinline__ void ldsm4(uint32_t* r, uint32_t addr)
{
    asm volatile("ldmatrix.sync.aligned.m8n8.x4.shared.b16 {%0,%1,%2,%3},[%4];"
                 : "=r"(r[0]), "=r"(r[1]), "=r"(r[2]), "=r"(r[3]) : "r"(addr));
}
__device__ __forceinline__ void ldsm4t(uint32_t* r, uint32_t addr)
{
    asm volatile("ldmatrix.sync.aligned.m8n8.x4.trans.shared.b16 {%0,%1,%2,%3},[%4];"
                 : "=r"(r[0]), "=r"(r[1]), "=r"(r[2]), "=r"(r[3]) : "r"(addr));
}
__device__ __forceinline__ void mma16816f(float* c, const uint32_t* a, const uint32_t* b)
{
    asm volatile(
        "mma.sync.aligned.m16n8k16.row.col.f32.f16.f16.f32 "
        "{%0,%1,%2,%3},{%4,%5,%6,%7},{%8,%9},{%0,%1,%2,%3};"
        : "+f"(c[0]), "+f"(c[1]), "+f"(c[2]), "+f"(c[3])
        : "r"(a[0]), "r"(a[1]), "r"(a[2]), "r"(a[3]), "r"(b[0]), "r"(b[1]));
}

// Fast exp: degree-5 poly for 2^f + exponent splice. x <= 0 expected.
__device__ __forceinline__ float fexp(float x)
{
    float t = fmaxf(x * 1.4426950408889634f, -126.0f);
    int n = __float2int_rn(t);
    float f = t - (float)n;
    float p = 1.33336621e-3f;
    p = fmaf(p, f, 9.61812910e-3f);
    p = fmaf(p, f, 5.55041087e-2f);
    p = fmaf(p, f, 2.40226507e-1f);
    p = fmaf(p, f, 6.93147182e-1f);
    p = fmaf(p, f, 1.0f);
    return __int_as_float(__float_as_int(p) + (n << 23));
}

// ---------------------------------------------------------------------------
// Tensor-core GEMM: C = A @ W^T + bias. Single fp16 both operands, 1 MMA.
// 512 threads / 16 warps (4m x 4n), warp tile 32x32 -> 32 acc regs/thread.
// 3-stage cp.async pipeline, one __syncthreads per k-tile.
// smem stage: A (10240 B) | Wh (10240) = 20480 B.
// ---------------------------------------------------------------------------
constexpr int STAGE_B = 20480;
constexpr int G_NSTG = 3;

__device__ __forceinline__ void stage_load512(
    const __half* Af, const __half* Wh,
    uint32_t sb, int bm, int bn, int k0, int tid)
{
#pragma unroll
    for (int i = 0; i < 2; ++i) {
        const int idx = tid + i * 512;          // 0..1023
        const int arr = idx >> 9;               // 0 = A, 1 = W
        const int within = idx & 511;
        const int row = within >> 2;            // 0..127
        const int cc = within & 3;              // 0..3
        uint32_t so = (uint32_t)(arr * 10240 + row * 80 + cc * 16);
        const __half* src = (arr == 0) ? Af + (size_t)(bm + row) * K_ + k0 + cc * 8
                                       : Wh + (size_t)(bn + row) * K_ + k0 + cc * 8;
        cp16(sb + so, src);
    }
    asm volatile("cp.async.commit_group;\n" ::);
}

template<int QKV>
__global__ __launch_bounds__(512, 2)
void mma_gemm(const float* __restrict__ b0p, const float* __restrict__ b1p,
              const float* __restrict__ b2p, float* __restrict__ C)
{
    extern __shared__ __half smem_raw[];
    const int tid = threadIdx.x;
    const int lane = tid & 31;
    const int warp = tid >> 5;       // 0..15
    const int wm = warp >> 2;        // 0..3
    const int wn = warp & 3;         // 0..3
    const int bm = blockIdx.y * 128;
    const int wsel = QKV ? (blockIdx.x >> 3) : 0;
    const int bn = (QKV ? (blockIdx.x & 7) : blockIdx.x) * 128;

    const __half* Af = g_af + (QKV ? XOFF : AOFF);
    const __half* Wh = g_wh + (size_t)(QKV ? wsel : 3) * N_ * K_;
    const float* bias = QKV ? (wsel == 0 ? b0p : wsel == 1 ? b1p : b2p) : b0p;

    uint32_t sbase = (uint32_t)__cvta_generic_to_shared(smem_raw);

    float acc[2][4][4];
#pragma unroll
    for (int mi = 0; mi < 2; ++mi)
#pragma unroll
        for (int ni = 0; ni < 4; ++ni)
#pragma unroll
            for (int r = 0; r < 4; ++r) acc[mi][ni][r] = 0.0f;

    constexpr int NT = K_ / 32;

    stage_load512(Af, Wh, sbase, bm, bn, 0, tid);
    stage_load512(Af, Wh, sbase + STAGE_B, bm, bn, 32, tid);

#pragma unroll 1
    for (int kt = 0; kt < NT; ++kt) {
        const int s = kt % G_NSTG;
        if (kt + 1 < NT) {
            asm volatile("cp.async.wait_group 1;\n" ::);
        } else {
            asm volatile("cp.async.wait_group 0;\n" ::);
        }
        __syncthreads();
        if (kt + 2 < NT)
            stage_load512(Af, Wh, sbase + ((kt + 2) % G_NSTG) * STAGE_B,
                          bm, bn, (kt + 2) * 32, tid);

        const uint32_t sb = sbase + s * STAGE_B;
#pragma unroll
        for (int k16 = 0; k16 < 2; ++k16) {
            uint32_t af[2][4];
#pragma unroll
            for (int mi = 0; mi < 2; ++mi) {
                int row = wm * 32 + mi * 16 + (lane & 15);
                uint32_t off = (uint32_t)(row * 80 + ((lane >> 4) * 8 + k16 * 16) * 2);
                ldsm4(af[mi], sb + off);
            }
#pragma unroll
            for (int nn = 0; nn < 2; ++nn) {
                int wrow = wn * 32 + nn * 16 + (lane & 7) + ((lane >> 4) << 3);
                uint32_t off = (uint32_t)(wrow * 80 + (((lane >> 3) & 1) * 8 + k16 * 16) * 2);
                uint32_t wh[4];
                ldsm4(wh, sb + 10240 + off);
                mma16816f(acc[0][nn * 2],     af[0], wh);
                mma16816f(acc[0][nn * 2 + 1], af[0], wh + 2);
                mma16816f(acc[1][nn * 2],     af[1], wh);
                mma16816f(acc[1][nn * 2 + 1], af[1], wh + 2);
            }
        }
    }

#pragma unroll
    for (int mi = 0; mi < 2; ++mi) {
#pragma unroll
        for (int ni = 0; ni < 4; ++ni) {
            const int r0 = bm + wm * 32 + mi * 16 + (lane >> 2);
            const int c0 = bn + wn * 32 + ni * 8 + (lane & 3) * 2;
            const float b0 = bias[c0];
            const float b1 = bias[c0 + 1];
            float2 v01 = make_float2(acc[mi][ni][0] + b0, acc[mi][ni][1] + b1);
            float2 v23 = make_float2(acc[mi][ni][2] + b0, acc[mi][ni][3] + b1);
            if (!QKV) {
                *(float2*)&C[(size_t)r0 * N_ + c0] = v01;
                *(float2*)&C[(size_t)(r0 + 8) * N_ + c0] = v23;
            } else {
                __half* dst = (wsel == 0) ? g_qf : (wsel == 1) ? g_kf : g_vf;
                const int h = c0 >> 6;
                const int d = c0 & (DK_ - 1);
#pragma unroll
                for (int rr = 0; rr < 2; ++rr) {
                    const int row = r0 + rr * 8;
                    const int b = row >> 11, t = row & (T_ - 1);
                    const float x0 = rr ? v23.x : v01.x;
                    const float x1 = rr ? v23.y : v01.y;
                    size_t off = (((size_t)b * H_ + h) * T_ + t) * DK_ + d;
                    *(__half2*)&dst[off] = __floats2half2_rn(x0, x1);
                }
            }
        }
    }
}

// ---------------------------------------------------------------------------
// Flash attention: single fp16 QK^T and PV, depth-2 fragment prefetch.
// Causal, online softmax. 128 threads, 64 query rows. 2 CTAs/SM.
// (unchanged from R13 — carried the win)
// ---------------------------------------------------------------------------
constexpr int AT_STRIDE = 72;
constexpr int AT_TILE = 64 * AT_STRIDE;
constexpr int AT_KVBASE = AT_TILE;                          // after Qf
constexpr int AT_STAGE = 2 * AT_TILE;                       // Kf,Vf
constexpr int AT_SMEM_ELEMS = AT_KVBASE + 2 * AT_STAGE;     // 23040
constexpr int AT_SMEM_BYTES = AT_SMEM_ELEMS * 2;            // 46080

__device__ __forceinline__ void at_load_kv(uint32_t sb, int stage, size_t gbase, int kt, int tid)
{
    uint32_t stbase = sb + (AT_KVBASE + stage * AT_STAGE) * 2;
    const __half* srcs[2] = {g_kf, g_vf};
#pragma unroll
    for (int i = 0; i < 8; ++i) {
        const int arr = i >> 2;
        const int within = (tid + (i & 3) * 128) & 511;
        const int row = within >> 3;
        const int cc = within & 7;
        uint32_t so = stbase + (arr * AT_TILE + row * AT_STRIDE + cc * 8) * 2;
        cp16(so, srcs[arr] + gbase + (size_t)(kt * 64 + row) * DK_ + cc * 8);
    }
    asm volatile("cp.async.commit_group;\n" ::);
}

__global__ __launch_bounds__(128, 2)
void attn_kernel()
{
    extern __shared__ __half at_sm[];
    uint32_t sb = (uint32_t)__cvta_generic_to_shared(at_sm);

    const int tid = threadIdx.x;
    const int lane = tid & 31;
    const int warp = tid >> 5;

    const int qt = (int)gridDim.x - 1 - (int)blockIdx.x;
    const int bh = blockIdx.y;
    const size_t gbase = (size_t)bh * T_ * DK_;

#pragma unroll
    for (int i = 0; i < 4; ++i) {
        const int within = tid + i * 128;
        const int row = within >> 3;
        const int cc = within & 7;
        uint32_t so = sb + (row * AT_STRIDE + cc * 8) * 2;
        cp16(so, g_qf + gbase + (size_t)(qt * 64 + row) * DK_ + cc * 8);
    }
    at_load_kv(sb, 0, gbase, 0, tid);

    float oAcc[8][4];
#pragma unroll
    for (int nt = 0; nt < 8; ++nt)
#pragma unroll
        for (int c = 0; c < 4; ++c) oAcc[nt][c] = 0.0f;

    float m0 = -1e30f, m1 = -1e30f, l0 = 0.0f, l1 = 0.0f;
    const int row0g = qt * 64 + warp * 16 + (lane >> 2);

    uint32_t qf[4][4];
    bool qloaded = false;

#pragma unroll 1
    for (int kt = 0; kt <= qt; ++kt) {
        const int s = kt & 1;
        asm volatile("cp.async.wait_group 0;\n" ::);
        __syncthreads();
        if (kt + 1 <= qt)
            at_load_kv(sb, s ^ 1, gbase, kt + 1, tid);

        if (!qloaded) {
            qloaded = true;
#pragma unroll
            for (int k16 = 0; k16 < 4; ++k16) {
                int row = warp * 16 + (lane & 15);
                uint32_t off = (uint32_t)(row * AT_STRIDE + (lane >> 4) * 8 + k16 * 16) * 2;
                ldsm4(qf[k16], sb + off);
            }
        }

        const uint32_t kvb = sb + (AT_KVBASE + s * AT_STAGE) * 2;

        // ---- S = Q @ K^T (flattened, depth-2 K-frag prefetch) ----
        float sAcc[8][4];
#pragma unroll
        for (int nt = 0; nt < 8; ++nt)
#pragma unroll
            for (int c = 0; c < 4; ++c) sAcc[nt][c] = 0.0f;

        const int krow0 = (lane & 7) + ((lane >> 4) << 3);
        const uint32_t kcol = ((lane >> 3) & 1) * 8;
        auto kaddr = [&](int it) -> uint32_t {
            const int k16 = it >> 2, np = it & 3;
            return kvb + (uint32_t)((np * 16 + krow0) * AT_STRIDE + kcol + k16 * 16) * 2;
        };
        {
            uint32_t kfb[3][4];
            ldsm4(kfb[0], kaddr(0));
            ldsm4(kfb[1], kaddr(1));
#pragma unroll
            for (int it = 0; it < 16; ++it) {
                if (it + 2 < 16) ldsm4(kfb[(it + 2) % 3], kaddr(it + 2));
                const int k16 = it >> 2, np = it & 3;
                const uint32_t* kf = kfb[it % 3];
                mma16816f(sAcc[np * 2],     qf[k16], kf);
                mma16816f(sAcc[np * 2 + 1], qf[k16], kf + 2);
            }
        }

        // ---- scale + causal mask ----
        const float invs = 0.125f;
        if (kt == qt) {
#pragma unroll
            for (int nt = 0; nt < 8; ++nt) {
                const int colb = kt * 64 + nt * 8 + (lane & 3) * 2;
#pragma unroll
                for (int c = 0; c < 4; ++c) {
                    const int col = colb + (c & 1);
                    const int row = row0g + ((c >> 1) << 3);
                    sAcc[nt][c] = (col <= row) ? sAcc[nt][c] * invs : -1e30f;
                }
            }
        } else {
#pragma unroll
            for (int nt = 0; nt < 8; ++nt)
#pragma unroll
                for (int c = 0; c < 4; ++c) sAcc[nt][c] *= invs;
        }

        // ---- online softmax ----
        float mx0 = -1e30f, mx1 = -1e30f;
#pragma unroll
        for (int nt = 0; nt < 8; ++nt) {
            mx0 = fmaxf(mx0, fmaxf(sAcc[nt][0], sAcc[nt][1]));
            mx1 = fmaxf(mx1, fmaxf(sAcc[nt][2], sAcc[nt][3]));
        }
        mx0 = fmaxf(mx0, __shfl_xor_sync(0xffffffffu, mx0, 1));
        mx0 = fmaxf(mx0, __shfl_xor_sync(0xffffffffu, mx0, 2));
        mx1 = fmaxf(mx1, __shfl_xor_sync(0xffffffffu, mx1, 1));
        mx1 = fmaxf(mx1, __shfl_xor_sync(0xffffffffu, mx1, 2));

        const float mn0 = fmaxf(m0, mx0);
        const float mn1 = fmaxf(m1, mx1);
        const float fac0 = fexp(m0 - mn0);
        const float fac1 = fexp(m1 - mn1);
        m0 = mn0; m1 = mn1;

        float sum0 = 0.0f, sum1 = 0.0f;
#pragma unroll
        for (int nt = 0; nt < 8; ++nt) {
            sAcc[nt][0] = fexp(sAcc[nt][0] - m0);
            sAcc[nt][1] = fexp(sAcc[nt][1] - m0);
            sAcc[nt][2] = fexp(sAcc[nt][2] - m1);
            sAcc[nt][3] = fexp(sAcc[nt][3] - m1);
            sum0 += sAcc[nt][0] + sAcc[nt][1];
            sum1 += sAcc[nt][2] + sAcc[nt][3];
        }
        sum0 += __shfl_xor_sync(0xffffffffu, sum0, 1);
        sum0 += __shfl_xor_sync(0xffffffffu, sum0, 2);
        sum1 += __shfl_xor_sync(0xffffffffu, sum1, 1);
        sum1 += __shfl_xor_sync(0xffffffffu, sum1, 2);
        l0 = l0 * fac0 + sum0;
        l1 = l1 * fac1 + sum1;

#pragma unroll
        for (int nt = 0; nt < 8; ++nt) {
            oAcc[nt][0] *= fac0; oAcc[nt][1] *= fac0;
            oAcc[nt][2] *= fac1; oAcc[nt][3] *= fac1;
        }

        // ---- O += P @ V (flattened, depth-2 V-frag prefetch) ----
        const uint32_t vb = kvb + AT_TILE * 2;
        const int vrow0 = (lane & 7) + 8 * ((lane >> 3) & 1);
        const int vcol0 = 8 * (lane >> 4);
        auto vaddr = [&](int it) -> uint32_t {
            const int c16 = it >> 2, np = it & 3;
            return vb + (uint32_t)((c16 * 16 + vrow0) * AT_STRIDE + np * 16 + vcol0) * 2;
        };
        {
            uint32_t vfb[3][4];
            uint32_t pa[4];
            ldsm4t(vfb[0], vaddr(0));
            ldsm4t(vfb[1], vaddr(1));
#pragma unroll
            for (int it = 0; it < 16; ++it) {
                if (it + 2 < 16) ldsm4t(vfb[(it + 2) % 3], vaddr(it + 2));
                const int c16 = it >> 2, np = it & 3;
                if (np == 0) {
#pragma unroll
                    for (int half = 0; half < 2; ++half) {
                        const float* pv = sAcc[2 * c16 + half];
                        __half2 p01 = __floats2half2_rn(pv[0], pv[1]);
                        __half2 p23 = __floats2half2_rn(pv[2], pv[3]);
                        pa[half * 2 + 0] = *(uint32_t*)&p01;
                        pa[half * 2 + 1] = *(uint32_t*)&p23;
                    }
                }
                const uint32_t* vf = vfb[it % 3];
                mma16816f(oAcc[np * 2],     pa, vf);
                mma16816f(oAcc[np * 2 + 1], pa, vf + 2);
            }
        }
    }

    // ---- epilogue ----
    const float inv0 = 1.0f / l0;
    const float inv1 = 1.0f / l1;
    const int b = bh >> 4;
    const int h = bh & 15;
#pragma unroll
    for (int rr = 0; rr < 2; ++rr) {
        const int t = qt * 64 + warp * 16 + (lane >> 2) + rr * 8;
        const float inv = rr ? inv1 : inv0;
        size_t rowoff = AOFF + ((size_t)b * T_ + t) * D_ + h * DK_ + (lane & 3) * 2;
#pragma unroll
        for (int nt = 0; nt < 8; ++nt) {
            *(__half2*)&g_af[rowoff + nt * 8] = __floats2half2_rn(
                oAcc[nt][rr * 2] * inv, oAcc[nt][rr * 2 + 1] * inv);
        }
    }
}

// ---------------------------------------------------------------------------
// Launch
// ---------------------------------------------------------------------------
extern "C" void kernel_launch(void* const* d_in, const int* in_sizes, int n_in,
                              void* d_out, int out_size)
{
    (void)in_sizes; (void)n_in; (void)out_size;
    const float* x  = (const float*)d_in[0];
    const float* Wq = (const float*)d_in[2];
    const float* Wk = (const float*)d_in[3];
    const float* Wv = (const float*)d_in[4];
    const float* Wo = (const float*)d_in[5];
    const float* bq = (const float*)d_in[6];
    const float* bk = (const float*)d_in[7];
    const float* bv = (const float*)d_in[8];
    const float* bo = (const float*)d_in[9];
    float* out = (float*)d_out;

    conv_all<<<NBX + 4 * NBW, 256>>>(x, Wq, Wk, Wv, Wo);

    const int gemm_smem = G_NSTG * STAGE_B;   // 61440
    cudaFuncSetAttribute(mma_gemm<1>, cudaFuncAttributeMaxDynamicSharedMemorySize, gemm_smem);
    cudaFuncSetAttribute(mma_gemm<0>, cudaFuncAttributeMaxDynamicSharedMemorySize, gemm_smem);
    cudaFuncSetAttribute(attn_kernel, cudaFuncAttributeMaxDynamicSharedMemorySize, AT_SMEM_BYTES);

    // Fused QKV projection: grid (3*8, 64), 512 threads
    mma_gemm<1><<<dim3(24, M_ / 128), 512, gemm_smem>>>(bq, bk, bv, nullptr);

    // Attention: 64 query rows per CTA, 2 CTAs/SM
    attn_kernel<<<dim3(T_ / 64, B_ * H_), 128, AT_SMEM_BYTES>>>();

    // Output projection, 512 threads
    mma_gemm<0><<<dim3(N_ / 128, M_ / 128), 512, gemm_smem>>>(bo, nullptr, nullptr, out);
}

// round 16
// speedup vs baseline: 1.0480x; 1.0480x over previous
#include <cuda_runtime.h>
#include <cuda_fp16.h>
#include <math.h>
#include <stdint.h>

// Problem constants
constexpr int B_ = 4;
constexpr int T_ = 2048;
constexpr int D_ = 1024;
constexpr int H_ = 16;
constexpr int DK_ = 64;
constexpr int M_ = B_ * T_;   // 8192
constexpr int N_ = D_;        // 1024
constexpr int K_ = D_;        // 1024

// fp16 arenas.
constexpr size_t XOFF = 0;
constexpr size_t AOFF = (size_t)M_ * K_;
constexpr size_t AF_SZ = AOFF + (size_t)M_ * D_;
__device__ __half g_af[AF_SZ];
__device__ __half g_wh[4ull * N_ * K_];

// Q/K/V single fp16, layout [B*H, T, DK]
constexpr size_t QKV_SZ = (size_t)B_ * H_ * T_ * DK_;
__device__ __half g_qf[QKV_SZ];
__device__ __half g_kf[QKV_SZ];
__device__ __half g_vf[QKV_SZ];

// ---------------------------------------------------------------------------
// Fused converter: x and W0..W3 -> single fp16. 16 floats/thread (MLP 4).
// ---------------------------------------------------------------------------
constexpr int NBX = (M_ * K_ / 16) / 256;   // 2048
constexpr int NBW = (N_ * K_ / 16) / 256;   // 256

__global__ void conv_all(const float* __restrict__ x,
                         const float* __restrict__ w0, const float* __restrict__ w1,
                         const float* __restrict__ w2, const float* __restrict__ w3)
{
    const int blk = blockIdx.x;
    const float* src;
    __half* dst;
    int i;
    if (blk < NBX) {
        src = x; dst = g_af;
        i = blk * 256 + threadIdx.x;
    } else {
        const int r = blk - NBX;
        const int w = r / NBW;
        src = (w == 0) ? w0 : (w == 1) ? w1 : (w == 2) ? w2 : w3;
        dst = g_wh + (size_t)w * N_ * K_;
        i = (r % NBW) * 256 + threadIdx.x;
    }
    const float4* p4 = (const float4*)src;
    float4 v0 = p4[4 * i + 0];
    float4 v1 = p4[4 * i + 1];
    float4 v2 = p4[4 * i + 2];
    float4 v3 = p4[4 * i + 3];
    __half2 h[8];
    h[0] = __floats2half2_rn(v0.x, v0.y);
    h[1] = __floats2half2_rn(v0.z, v0.w);
    h[2] = __floats2half2_rn(v1.x, v1.y);
    h[3] = __floats2half2_rn(v1.z, v1.w);
    h[4] = __floats2half2_rn(v2.x, v2.y);
    h[5] = __floats2half2_rn(v2.z, v2.w);
    h[6] = __floats2half2_rn(v3.x, v3.y);
    h[7] = __floats2half2_rn(v3.z, v3.w);
    *(uint4*)(dst + (size_t)i * 16)     = *(uint4*)&h[0];
    *(uint4*)(dst + (size_t)i * 16 + 8) = *(uint4*)&h[4];
}

// ---------------------------------------------------------------------------
// MMA helpers
// ---------------------------------------------------------------------------
__device__ __forceinline__ void cp16(uint32_t dst, const void* src)
{
    asm volatile("cp.async.cg.shared.global [%0],[%1],16;\n" :: "r"(dst), "l"(src));
}
__device__ __forceinline__ void ldsm4(uint32_t* r, uint32_t addr)
{
    asm volatile("ldmatrix.sync.aligned.m8n8.x4.shared.b16 {%0,%1,%2,%3},[%4];"
                 : "=r"(r[0]), "=r"(r[1]), "=r"(r[2]), "=r"(r[3]) : "r"(addr));
}
__device__ __forceinline__ void ldsm4t(uint32_t* r, uint32_t addr)
{
    asm volatile("ldmatrix.sync.aligned.m8n8.x4.trans.shared.b16 {%0,%1,%2,%3},[%4];"
                 : "=r"(r[0]), "=r"(r[1]), "=r"(r[2]), "=r"(r[3]) : "r"(addr));
}
__device__ __forceinline__ void mma16816f(float* c, const uint32_t* a, const uint32_t* b)
{
    asm volatile(
        "mma.sync.aligned.m16n8k16.row.col.f32.f16.f16.f32 "
        "{%0,%1,%2,%3},{%4,%5,%6,%7},{%8,%9},{%0,%1,%2,%3};"
        : "+f"(c[0]), "+f"(c[1]), "+f"(c[2]), "+f"(c[3])
        : "r"(a[0]), "r"(a[1]), "r"(a[2]), "r"(a[3]), "r"(b[0]), "r"(b[1]));
}

// Fast exp: degree-5 poly for 2^f + exponent splice. x <= 0 expected.
__device__ __forceinline__ float fexp(float x)
{
    float t = fmaxf(x * 1.4426950408889634f, -126.0f);
    int n = __float2int_rn(t);
    float f = t - (float)n;
    float p = 1.33336621e-3f;
    p = fmaf(p, f, 9.61812910e-3f);
    p = fmaf(p, f, 5.55041087e-2f);
    p = fmaf(p, f, 2.40226507e-1f);
    p = fmaf(p, f, 6.93147182e-1f);
    p = fmaf(p, f, 1.0f);
    return __int_as_float(__float_as_int(p) + (n << 23));
}

// ---------------------------------------------------------------------------
// Tensor-core GEMM (exact R13 winner): single fp16, 1 MMA per product.
// 256 threads / 8 warps (4m x 2n), warp tile 32x64. 3-stage cp.async, BK=32.
// ---------------------------------------------------------------------------
constexpr int STAGE_B = 20480;
constexpr int G_NSTG = 3;

__device__ __forceinline__ void stage_load(
    const __half* Af, const __half* Wh,
    uint32_t sb, int bm, int bn, int k0, int tid)
{
#pragma unroll
    for (int i = 0; i < 4; ++i) {
        const int arr = i >> 1;
        const int within = tid + (i & 1) * 256;
        const int row = within >> 2;
        const int cc = within & 3;
        uint32_t so = (uint32_t)(arr * 10240 + row * 80 + cc * 16);
        const __half* src = (arr == 0) ? Af + (size_t)(bm + row) * K_ + k0 + cc * 8
                                       : Wh + (size_t)(bn + row) * K_ + k0 + cc * 8;
        cp16(sb + so, src);
    }
    asm volatile("cp.async.commit_group;\n" ::);
}

template<int QKV>
__global__ __launch_bounds__(256, 2)
void mma_gemm(const float* __restrict__ b0p, const float* __restrict__ b1p,
              const float* __restrict__ b2p, float* __restrict__ C)
{
    extern __shared__ __half smem_raw[];
    const int tid = threadIdx.x;
    const int lane = tid & 31;
    const int warp = tid >> 5;
    const int wm = warp >> 1;
    const int wn = warp & 1;
    const int bm = blockIdx.y * 128;
    const int wsel = QKV ? (blockIdx.x >> 3) : 0;
    const int bn = (QKV ? (blockIdx.x & 7) : blockIdx.x) * 128;

    const __half* Af = g_af + (QKV ? XOFF : AOFF);
    const __half* Wh = g_wh + (size_t)(QKV ? wsel : 3) * N_ * K_;
    const float* bias = QKV ? (wsel == 0 ? b0p : wsel == 1 ? b1p : b2p) : b0p;

    uint32_t sbase = (uint32_t)__cvta_generic_to_shared(smem_raw);

    float acc[2][8][4];
#pragma unroll
    for (int mi = 0; mi < 2; ++mi)
#pragma unroll
        for (int ni = 0; ni < 8; ++ni)
#pragma unroll
            for (int r = 0; r < 4; ++r) acc[mi][ni][r] = 0.0f;

    constexpr int NT = K_ / 32;

    stage_load(Af, Wh, sbase, bm, bn, 0, tid);
    stage_load(Af, Wh, sbase + STAGE_B, bm, bn, 32, tid);

#pragma unroll 1
    for (int kt = 0; kt < NT; ++kt) {
        const int s = kt % G_NSTG;
        if (kt + 1 < NT) {
            asm volatile("cp.async.wait_group 1;\n" ::);
        } else {
            asm volatile("cp.async.wait_group 0;\n" ::);
        }
        __syncthreads();
        if (kt + 2 < NT)
            stage_load(Af, Wh, sbase + ((kt + 2) % G_NSTG) * STAGE_B,
                       bm, bn, (kt + 2) * 32, tid);

        const uint32_t sb = sbase + s * STAGE_B;
#pragma unroll
        for (int k16 = 0; k16 < 2; ++k16) {
            uint32_t af[2][4];
#pragma unroll
            for (int mi = 0; mi < 2; ++mi) {
                int row = wm * 32 + mi * 16 + (lane & 15);
                uint32_t off = (uint32_t)(row * 80 + ((lane >> 4) * 8 + k16 * 16) * 2);
                ldsm4(af[mi], sb + off);
            }
#pragma unroll
            for (int nq = 0; nq < 4; ++nq) {
                int wrow = wn * 64 + nq * 16 + (lane & 7) + ((lane >> 4) << 3);
                uint32_t off = (uint32_t)(wrow * 80 + (((lane >> 3) & 1) * 8 + k16 * 16) * 2);
                uint32_t wh[4];
                ldsm4(wh, sb + 10240 + off);
                mma16816f(acc[0][nq * 2],     af[0], wh);
                mma16816f(acc[0][nq * 2 + 1], af[0], wh + 2);
                mma16816f(acc[1][nq * 2],     af[1], wh);
                mma16816f(acc[1][nq * 2 + 1], af[1], wh + 2);
            }
        }
    }

#pragma unroll
    for (int mi = 0; mi < 2; ++mi) {
#pragma unroll
        for (int ni = 0; ni < 8; ++ni) {
            const int r0 = bm + wm * 32 + mi * 16 + (lane >> 2);
            const int c0 = bn + wn * 64 + ni * 8 + (lane & 3) * 2;
            const float b0 = bias[c0];
            const float b1 = bias[c0 + 1];
            float2 v01 = make_float2(acc[mi][ni][0] + b0, acc[mi][ni][1] + b1);
            float2 v23 = make_float2(acc[mi][ni][2] + b0, acc[mi][ni][3] + b1);
            if (!QKV) {
                *(float2*)&C[(size_t)r0 * N_ + c0] = v01;
                *(float2*)&C[(size_t)(r0 + 8) * N_ + c0] = v23;
            } else {
                __half* dst = (wsel == 0) ? g_qf : (wsel == 1) ? g_kf : g_vf;
                const int h = c0 >> 6;
                const int d = c0 & (DK_ - 1);
#pragma unroll
                for (int rr = 0; rr < 2; ++rr) {
                    const int row = r0 + rr * 8;
                    const int b = row >> 11, t = row & (T_ - 1);
                    const float x0 = rr ? v23.x : v01.x;
                    const float x1 = rr ? v23.y : v01.y;
                    size_t off = (((size_t)b * H_ + h) * T_ + t) * DK_ + d;
                    *(__half2*)&dst[off] = __floats2half2_rn(x0, x1);
                }
            }
        }
    }
}

// ---------------------------------------------------------------------------
// Flash attention (exact R13 winner): fp16 QK^T and PV, depth-2 frag prefetch.
// ---------------------------------------------------------------------------
constexpr int AT_STRIDE = 72;
constexpr int AT_TILE = 64 * AT_STRIDE;
constexpr int AT_KVBASE = AT_TILE;
constexpr int AT_STAGE = 2 * AT_TILE;
constexpr int AT_SMEM_ELEMS = AT_KVBASE + 2 * AT_STAGE;
constexpr int AT_SMEM_BYTES = AT_SMEM_ELEMS * 2;   // 46080

__device__ __forceinline__ void at_load_kv(uint32_t sb, int stage, size_t gbase, int kt, int tid)
{
    uint32_t stbase = sb + (AT_KVBASE + stage * AT_STAGE) * 2;
    const __half* srcs[2] = {g_kf, g_vf};
#pragma unroll
    for (int i = 0; i < 8; ++i) {
        const int arr = i >> 2;
        const int within = (tid + (i & 3) * 128) & 511;
        const int row = within >> 3;
        const int cc = within & 7;
        uint32_t so = stbase + (arr * AT_TILE + row * AT_STRIDE + cc * 8) * 2;
        cp16(so, srcs[arr] + gbase + (size_t)(kt * 64 + row) * DK_ + cc * 8);
    }
    asm volatile("cp.async.commit_group;\n" ::);
}

__global__ __launch_bounds__(128, 2)
void attn_kernel()
{
    extern __shared__ __half at_sm[];
    uint32_t sb = (uint32_t)__cvta_generic_to_shared(at_sm);

    const int tid = threadIdx.x;
    const int lane = tid & 31;
    const int warp = tid >> 5;

    const int qt = (int)gridDim.x - 1 - (int)blockIdx.x;
    const int bh = blockIdx.y;
    const size_t gbase = (size_t)bh * T_ * DK_;

#pragma unroll
    for (int i = 0; i < 4; ++i) {
        const int within = tid + i * 128;
        const int row = within >> 3;
        const int cc = within & 7;
        uint32_t so = sb + (row * AT_STRIDE + cc * 8) * 2;
        cp16(so, g_qf + gbase + (size_t)(qt * 64 + row) * DK_ + cc * 8);
    }
    at_load_kv(sb, 0, gbase, 0, tid);

    float oAcc[8][4];
#pragma unroll
    for (int nt = 0; nt < 8; ++nt)
#pragma unroll
        for (int c = 0; c < 4; ++c) oAcc[nt][c] = 0.0f;

    float m0 = -1e30f, m1 = -1e30f, l0 = 0.0f, l1 = 0.0f;
    const int row0g = qt * 64 + warp * 16 + (lane >> 2);

    uint32_t qf[4][4];
    bool qloaded = false;

#pragma unroll 1
    for (int kt = 0; kt <= qt; ++kt) {
        const int s = kt & 1;
        asm volatile("cp.async.wait_group 0;\n" ::);
        __syncthreads();
        if (kt + 1 <= qt)
            at_load_kv(sb, s ^ 1, gbase, kt + 1, tid);

        if (!qloaded) {
            qloaded = true;
#pragma unroll
            for (int k16 = 0; k16 < 4; ++k16) {
                int row = warp * 16 + (lane & 15);
                uint32_t off = (uint32_t)(row * AT_STRIDE + (lane >> 4) * 8 + k16 * 16) * 2;
                ldsm4(qf[k16], sb + off);
            }
        }

        const uint32_t kvb = sb + (AT_KVBASE + s * AT_STAGE) * 2;

        // ---- S = Q @ K^T (flattened, depth-2 K-frag prefetch) ----
        float sAcc[8][4];
#pragma unroll
        for (int nt = 0; nt < 8; ++nt)
#pragma unroll
            for (int c = 0; c < 4; ++c) sAcc[nt][c] = 0.0f;

        const int krow0 = (lane & 7) + ((lane >> 4) << 3);
        const uint32_t kcol = ((lane >> 3) & 1) * 8;
        auto kaddr = [&](int it) -> uint32_t {
            const int k16 = it >> 2, np = it & 3;
            return kvb + (uint32_t)((np * 16 + krow0) * AT_STRIDE + kcol + k16 * 16) * 2;
        };
        {
            uint32_t kfb[3][4];
            ldsm4(kfb[0], kaddr(0));
            ldsm4(kfb[1], kaddr(1));
#pragma unroll
            for (int it = 0; it < 16; ++it) {
                if (it + 2 < 16) ldsm4(kfb[(it + 2) % 3], kaddr(it + 2));
                const int k16 = it >> 2, np = it & 3;
                const uint32_t* kf = kfb[it % 3];
                mma16816f(sAcc[np * 2],     qf[k16], kf);
                mma16816f(sAcc[np * 2 + 1], qf[k16], kf + 2);
            }
        }

        // ---- scale + causal mask ----
        const float invs = 0.125f;
        if (kt == qt) {
#pragma unroll
            for (int nt = 0; nt < 8; ++nt) {
                const int colb = kt * 64 + nt * 8 + (lane & 3) * 2;
#pragma unroll
                for (int c = 0; c < 4; ++c) {
                    const int col = colb + (c & 1);
                    const int row = row0g + ((c >> 1) << 3);
                    sAcc[nt][c] = (col <= row) ? sAcc[nt][c] * invs : -1e30f;
                }
            }
        } else {
#pragma unroll
            for (int nt = 0; nt < 8; ++nt)
#pragma unroll
                for (int c = 0; c < 4; ++c) sAcc[nt][c] *= invs;
        }

        // ---- online softmax ----
        float mx0 = -1e30f, mx1 = -1e30f;
#pragma unroll
        for (int nt = 0; nt < 8; ++nt) {
            mx0 = fmaxf(mx0, fmaxf(sAcc[nt][0], sAcc[nt][1]));
            mx1 = fmaxf(mx1, fmaxf(sAcc[nt][2], sAcc[nt][3]));
        }
        mx0 = fmaxf(mx0, __shfl_xor_sync(0xffffffffu, mx0, 1));
        mx0 = fmaxf(mx0, __shfl_xor_sync(0xffffffffu, mx0, 2));
        mx1 = fmaxf(mx1, __shfl_xor_sync(0xffffffffu, mx1, 1));
        mx1 = fmaxf(mx1, __shfl_xor_sync(0xffffffffu, mx1, 2));

        const float mn0 = fmaxf(m0, mx0);
        const float mn1 = fmaxf(m1, mx1);
        const float fac0 = fexp(m0 - mn0);
        const float fac1 = fexp(m1 - mn1);
        m0 = mn0; m1 = mn1;

        float sum0 = 0.0f, sum1 = 0.0f;
#pragma unroll
        for (int nt = 0; nt < 8; ++nt) {
            sAcc[nt][0] = fexp(sAcc[nt][0] - m0);
            sAcc[nt][1] = fexp(sAcc[nt][1] - m0);
            sAcc[nt][2] = fexp(sAcc[nt][2] - m1);
            sAcc[nt][3] = fexp(sAcc[nt][3] - m1);
            sum0 += sAcc[nt][0] + sAcc[nt][1];
            sum1 += sAcc[nt][2] + sAcc[nt][3];
        }
        sum0 += __shfl_xor_sync(0xffffffffu, sum0, 1);
        sum0 += __shfl_xor_sync(0xffffffffu, sum0, 2);
        sum1 += __shfl_xor_sync(0xffffffffu, sum1, 1);
        sum1 += __shfl_xor_sync(0xffffffffu, sum1, 2);
        l0 = l0 * fac0 + sum0;
        l1 = l1 * fac1 + sum1;

#pragma unroll
        for (int nt = 0; nt < 8; ++nt) {
            oAcc[nt][0] *= fac0; oAcc[nt][1] *= fac0;
            oAcc[nt][2] *= fac1; oAcc[nt][3] *= fac1;
        }

        // ---- O += P @ V (flattened, depth-2 V-frag prefetch) ----
        const uint32_t vb = kvb + AT_TILE * 2;
        const int vrow0 = (lane & 7) + 8 * ((lane >> 3) & 1);
        const int vcol0 = 8 * (lane >> 4);
        auto vaddr = [&](int it) -> uint32_t {
            const int c16 = it >> 2, np = it & 3;
            return vb + (uint32_t)((c16 * 16 + vrow0) * AT_STRIDE + np * 16 + vcol0) * 2;
        };
        {
            uint32_t vfb[3][4];
            uint32_t pa[4];
            ldsm4t(vfb[0], vaddr(0));
            ldsm4t(vfb[1], vaddr(1));
#pragma unroll
            for (int it = 0; it < 16; ++it) {
                if (it + 2 < 16) ldsm4t(vfb[(it + 2) % 3], vaddr(it + 2));
                const int c16 = it >> 2, np = it & 3;
                if (np == 0) {
#pragma unroll
                    for (int half = 0; half < 2; ++half) {
                        const float* pv = sAcc[2 * c16 + half];
                        __half2 p01 = __floats2half2_rn(pv[0], pv[1]);
                        __half2 p23 = __floats2half2_rn(pv[2], pv[3]);
                        pa[half * 2 + 0] = *(uint32_t*)&p01;
                        pa[half * 2 + 1] = *(uint32_t*)&p23;
                    }
                }
                const uint32_t* vf = vfb[it % 3];
                mma16816f(oAcc[np * 2],     pa, vf);
                mma16816f(oAcc[np * 2 + 1], pa, vf + 2);
            }
        }
    }

    // ---- epilogue ----
    const float inv0 = 1.0f / l0;
    const float inv1 = 1.0f / l1;
    const int b = bh >> 4;
    const int h = bh & 15;
#pragma unroll
    for (int rr = 0; rr < 2; ++rr) {
        const int t = qt * 64 + warp * 16 + (lane >> 2) + rr * 8;
        const float inv = rr ? inv1 : inv0;
        size_t rowoff = AOFF + ((size_t)b * T_ + t) * D_ + h * DK_ + (lane & 3) * 2;
#pragma unroll
        for (int nt = 0; nt < 8; ++nt) {
            *(__half2*)&g_af[rowoff + nt * 8] = __floats2half2_rn(
                oAcc[nt][rr * 2] * inv, oAcc[nt][rr * 2 + 1] * inv);
        }
    }
}

// ---------------------------------------------------------------------------
// Launch
// ---------------------------------------------------------------------------
extern "C" void kernel_launch(void* const* d_in, const int* in_sizes, int n_in,
                              void* d_out, int out_size)
{
    (void)in_sizes; (void)n_in; (void)out_size;
    const float* x  = (const float*)d_in[0];
    const float* Wq = (const float*)d_in[2];
    const float* Wk = (const float*)d_in[3];
    const float* Wv = (const float*)d_in[4];
    const float* Wo = (const float*)d_in[5];
    const float* bq = (const float*)d_in[6];
    const float* bk = (const float*)d_in[7];
    const float* bv = (const float*)d_in[8];
    const float* bo = (const float*)d_in[9];
    float* out = (float*)d_out;

    conv_all<<<NBX + 4 * NBW, 256>>>(x, Wq, Wk, Wv, Wo);

    const int gemm_smem = G_NSTG * STAGE_B;   // 61440
    cudaFuncSetAttribute(mma_gemm<1>, cudaFuncAttributeMaxDynamicSharedMemorySize, gemm_smem);
    cudaFuncSetAttribute(mma_gemm<0>, cudaFuncAttributeMaxDynamicSharedMemorySize, gemm_smem);
    cudaFuncSetAttribute(attn_kernel, cudaFuncAttributeMaxDynamicSharedMemorySize, AT_SMEM_BYTES);

    // Fused QKV projection: grid (3*8, 64), 256 threads (R13 config)
    mma_gemm<1><<<dim3(24, M_ / 128), 256, gemm_smem>>>(bq, bk, bv, nullptr);

    // Attention: 64 query rows per CTA, 2 CTAs/SM
    attn_kernel<<<dim3(T_ / 64, B_ * H_), 128, AT_SMEM_BYTES>>>();

    // Output projection
    mma_gemm<0><<<dim3(N_ / 128, M_ / 128), 256, gemm_smem>>>(bo, nullptr, nullptr, out);
}

// round 17
// speedup vs baseline: 1.1140x; 1.0630x over previous
#include <cuda_runtime.h>
#include <cuda_fp16.h>
#include <math.h>
#include <stdint.h>

// Problem constants
constexpr int B_ = 4;
constexpr int T_ = 2048;
constexpr int D_ = 1024;
constexpr int H_ = 16;
constexpr int DK_ = 64;
constexpr int M_ = B_ * T_;   // 8192
constexpr int N_ = D_;        // 1024
constexpr int K_ = D_;        // 1024

// fp16 arenas.
constexpr size_t XOFF = 0;
constexpr size_t AOFF = (size_t)M_ * K_;
constexpr size_t AF_SZ = AOFF + (size_t)M_ * D_;
__device__ __half g_af[AF_SZ];
__device__ __half g_wh[4ull * N_ * K_];

// Q/K/V single fp16, layout [B*H, T, DK]
constexpr size_t QKV_SZ = (size_t)B_ * H_ * T_ * DK_;
__device__ __half g_qf[QKV_SZ];
__device__ __half g_kf[QKV_SZ];
__device__ __half g_vf[QKV_SZ];

// ---------------------------------------------------------------------------
// Fused converter: x and W0..W3 -> single fp16. 16 floats/thread.
// ---------------------------------------------------------------------------
constexpr int NBX = (M_ * K_ / 16) / 256;   // 2048
constexpr int NBW = (N_ * K_ / 16) / 256;   // 256

__global__ void conv_all(const float* __restrict__ x,
                         const float* __restrict__ w0, const float* __restrict__ w1,
                         const float* __restrict__ w2, const float* __restrict__ w3)
{
    const int blk = blockIdx.x;
    const float* src;
    __half* dst;
    int i;
    if (blk < NBX) {
        src = x; dst = g_af;
        i = blk * 256 + threadIdx.x;
    } else {
        const int r = blk - NBX;
        const int w = r / NBW;
        src = (w == 0) ? w0 : (w == 1) ? w1 : (w == 2) ? w2 : w3;
        dst = g_wh + (size_t)w * N_ * K_;
        i = (r % NBW) * 256 + threadIdx.x;
    }
    const float4* p4 = (const float4*)src;
    float4 v0 = p4[4 * i + 0];
    float4 v1 = p4[4 * i + 1];
    float4 v2 = p4[4 * i + 2];
    float4 v3 = p4[4 * i + 3];
    __half2 h[8];
    h[0] = __floats2half2_rn(v0.x, v0.y);
    h[1] = __floats2half2_rn(v0.z, v0.w);
    h[2] = __floats2half2_rn(v1.x, v1.y);
    h[3] = __floats2half2_rn(v1.z, v1.w);
    h[4] = __floats2half2_rn(v2.x, v2.y);
    h[5] = __floats2half2_rn(v2.z, v2.w);
    h[6] = __floats2half2_rn(v3.x, v3.y);
    h[7] = __floats2half2_rn(v3.z, v3.w);
    *(uint4*)(dst + (size_t)i * 16)     = *(uint4*)&h[0];
    *(uint4*)(dst + (size_t)i * 16 + 8) = *(uint4*)&h[4];
}

// ---------------------------------------------------------------------------
// MMA helpers
// ---------------------------------------------------------------------------
__device__ __forceinline__ void cp16(uint32_t dst, const void* src)
{
    asm volatile("cp.async.cg.shared.global [%0],[%1],16;\n" :: "r"(dst), "l"(src));
}
__device__ __forceinline__ void ldsm4(uint32_t* r, uint32_t addr)
{
    asm volatile("ldmatrix.sync.aligned.m8n8.x4.shared.b16 {%0,%1,%2,%3},[%4];"
                 : "=r"(r[0]), "=r"(r[1]), "=r"(r[2]), "=r"(r[3]) : "r"(addr));
}
__device__ __forceinline__ void ldsm4t(uint32_t* r, uint32_t addr)
{
    asm volatile("ldmatrix.sync.aligned.m8n8.x4.trans.shared.b16 {%0,%1,%2,%3},[%4];"
                 : "=r"(r[0]), "=r"(r[1]), "=r"(r[2]), "=r"(r[3]) : "r"(addr));
}
__device__ __forceinline__ void mma16816f(float* c, const uint32_t* a, const uint32_t* b)
{
    asm volatile(
        "mma.sync.aligned.m16n8k16.row.col.f32.f16.f16.f32 "
        "{%0,%1,%2,%3},{%4,%5,%6,%7},{%8,%9},{%0,%1,%2,%3};"
        : "+f"(c[0]), "+f"(c[1]), "+f"(c[2]), "+f"(c[3])
        : "r"(a[0]), "r"(a[1]), "r"(a[2]), "r"(a[3]), "r"(b[0]), "r"(b[1]));
}

// Fast exp: degree-5 poly for 2^f + exponent splice. x <= 0 expected.
__device__ __forceinline__ float fexp(float x)
{
    float t = fmaxf(x * 1.4426950408889634f, -126.0f);
    int n = __float2int_rn(t);
    float f = t - (float)n;
    float p = 1.33336621e-3f;
    p = fmaf(p, f, 9.61812910e-3f);
    p = fmaf(p, f, 5.55041087e-2f);
    p = fmaf(p, f, 2.40226507e-1f);
    p = fmaf(p, f, 6.93147182e-1f);
    p = fmaf(p, f, 1.0f);
    return __int_as_float(__float_as_int(p) + (n << 23));
}

// ---------------------------------------------------------------------------
// Tensor-core GEMM: single fp16, 1 MMA. BK=64, 2-stage pipeline (16 syncs).
// 256 threads / 8 warps (4m x 2n), warp tile 32x64.
// smem tile: 128 rows x 72-elem stride (144 B). A at 0, W at 18432 B.
// stage = 36864 B, 2 stages = 73728 B.
// ---------------------------------------------------------------------------
constexpr int G_STRIDE = 72;                       // elems
constexpr int G_ARR = 128 * G_STRIDE * 2;          // 18432 B per array
constexpr int STAGE_B = 2 * G_ARR;                 // 36864
constexpr int G_NSTG = 2;

__device__ __forceinline__ void stage_load(
    const __half* Af, const __half* Wh,
    uint32_t sb, int bm, int bn, int k0, int tid)
{
#pragma unroll
    for (int i = 0; i < 8; ++i) {
        const int idx = tid + i * 256;          // 0..2047
        const int arr = idx >> 10;              // 0 = A, 1 = W
        const int within = idx & 1023;
        const int row = within >> 3;            // 0..127
        const int cc = within & 7;              // 0..7
        uint32_t so = (uint32_t)(arr * G_ARR + row * (G_STRIDE * 2) + cc * 16);
        const __half* src = (arr == 0) ? Af + (size_t)(bm + row) * K_ + k0 + cc * 8
                                       : Wh + (size_t)(bn + row) * K_ + k0 + cc * 8;
        cp16(sb + so, src);
    }
    asm volatile("cp.async.commit_group;\n" ::);
}

template<int QKV>
__global__ __launch_bounds__(256, 2)
void mma_gemm(const float* __restrict__ b0p, const float* __restrict__ b1p,
              const float* __restrict__ b2p, float* __restrict__ C)
{
    extern __shared__ __half smem_raw[];
    const int tid = threadIdx.x;
    const int lane = tid & 31;
    const int warp = tid >> 5;
    const int wm = warp >> 1;
    const int wn = warp & 1;
    const int bm = blockIdx.y * 128;
    const int wsel = QKV ? (blockIdx.x >> 3) : 0;
    const int bn = (QKV ? (blockIdx.x & 7) : blockIdx.x) * 128;

    const __half* Af = g_af + (QKV ? XOFF : AOFF);
    const __half* Wh = g_wh + (size_t)(QKV ? wsel : 3) * N_ * K_;
    const float* bias = QKV ? (wsel == 0 ? b0p : wsel == 1 ? b1p : b2p) : b0p;

    uint32_t sbase = (uint32_t)__cvta_generic_to_shared(smem_raw);

    float acc[2][8][4];
#pragma unroll
    for (int mi = 0; mi < 2; ++mi)
#pragma unroll
        for (int ni = 0; ni < 8; ++ni)
#pragma unroll
            for (int r = 0; r < 4; ++r) acc[mi][ni][r] = 0.0f;

    constexpr int NT = K_ / 64;   // 16

    stage_load(Af, Wh, sbase, bm, bn, 0, tid);

#pragma unroll 1
    for (int kt = 0; kt < NT; ++kt) {
        const int s = kt & 1;
        asm volatile("cp.async.wait_group 0;\n" ::);
        __syncthreads();
        if (kt + 1 < NT)
            stage_load(Af, Wh, sbase + (s ^ 1) * STAGE_B, bm, bn, (kt + 1) * 64, tid);

        const uint32_t sb = sbase + s * STAGE_B;
#pragma unroll
        for (int k16 = 0; k16 < 4; ++k16) {
            uint32_t af[2][4];
#pragma unroll
            for (int mi = 0; mi < 2; ++mi) {
                int row = wm * 32 + mi * 16 + (lane & 15);
                uint32_t off = (uint32_t)(row * (G_STRIDE * 2) + ((lane >> 4) * 8 + k16 * 16) * 2);
                ldsm4(af[mi], sb + off);
            }
#pragma unroll
            for (int nq = 0; nq < 4; ++nq) {
                int wrow = wn * 64 + nq * 16 + (lane & 7) + ((lane >> 4) << 3);
                uint32_t off = (uint32_t)(wrow * (G_STRIDE * 2) + (((lane >> 3) & 1) * 8 + k16 * 16) * 2);
                uint32_t wh[4];
                ldsm4(wh, sb + G_ARR + off);
                mma16816f(acc[0][nq * 2],     af[0], wh);
                mma16816f(acc[0][nq * 2 + 1], af[0], wh + 2);
                mma16816f(acc[1][nq * 2],     af[1], wh);
                mma16816f(acc[1][nq * 2 + 1], af[1], wh + 2);
            }
        }
    }

#pragma unroll
    for (int mi = 0; mi < 2; ++mi) {
#pragma unroll
        for (int ni = 0; ni < 8; ++ni) {
            const int r0 = bm + wm * 32 + mi * 16 + (lane >> 2);
            const int c0 = bn + wn * 64 + ni * 8 + (lane & 3) * 2;
            const float b0 = bias[c0];
            const float b1 = bias[c0 + 1];
            float2 v01 = make_float2(acc[mi][ni][0] + b0, acc[mi][ni][1] + b1);
            float2 v23 = make_float2(acc[mi][ni][2] + b0, acc[mi][ni][3] + b1);
            if (!QKV) {
                *(float2*)&C[(size_t)r0 * N_ + c0] = v01;
                *(float2*)&C[(size_t)(r0 + 8) * N_ + c0] = v23;
            } else {
                __half* dst = (wsel == 0) ? g_qf : (wsel == 1) ? g_kf : g_vf;
                const int h = c0 >> 6;
                const int d = c0 & (DK_ - 1);
#pragma unroll
                for (int rr = 0; rr < 2; ++rr) {
                    const int row = r0 + rr * 8;
                    const int b = row >> 11, t = row & (T_ - 1);
                    const float x0 = rr ? v23.x : v01.x;
                    const float x1 = rr ? v23.y : v01.y;
                    size_t off = (((size_t)b * H_ + h) * T_ + t) * DK_ + d;
                    *(__half2*)&dst[off] = __floats2half2_rn(x0, x1);
                }
            }
        }
    }
}

// ---------------------------------------------------------------------------
// Flash attention (exact R13 winner): fp16 QK^T and PV, depth-2 frag prefetch.
// ---------------------------------------------------------------------------
constexpr int AT_STRIDE = 72;
constexpr int AT_TILE = 64 * AT_STRIDE;
constexpr int AT_KVBASE = AT_TILE;
constexpr int AT_STAGE = 2 * AT_TILE;
constexpr int AT_SMEM_ELEMS = AT_KVBASE + 2 * AT_STAGE;
constexpr int AT_SMEM_BYTES = AT_SMEM_ELEMS * 2;   // 46080

__device__ __forceinline__ void at_load_kv(uint32_t sb, int stage, size_t gbase, int kt, int tid)
{
    uint32_t stbase = sb + (AT_KVBASE + stage * AT_STAGE) * 2;
    const __half* srcs[2] = {g_kf, g_vf};
#pragma unroll
    for (int i = 0; i < 8; ++i) {
        const int arr = i >> 2;
        const int within = (tid + (i & 3) * 128) & 511;
        const int row = within >> 3;
        const int cc = within & 7;
        uint32_t so = stbase + (arr * AT_TILE + row * AT_STRIDE + cc * 8) * 2;
        cp16(so, srcs[arr] + gbase + (size_t)(kt * 64 + row) * DK_ + cc * 8);
    }
    asm volatile("cp.async.commit_group;\n" ::);
}

__global__ __launch_bounds__(128, 2)
void attn_kernel()
{
    extern __shared__ __half at_sm[];
    uint32_t sb = (uint32_t)__cvta_generic_to_shared(at_sm);

    const int tid = threadIdx.x;
    const int lane = tid & 31;
    const int warp = tid >> 5;

    const int qt = (int)gridDim.x - 1 - (int)blockIdx.x;
    const int bh = blockIdx.y;
    const size_t gbase = (size_t)bh * T_ * DK_;

#pragma unroll
    for (int i = 0; i < 4; ++i) {
        const int within = tid + i * 128;
        const int row = within >> 3;
        const int cc = within & 7;
        uint32_t so = sb + (row * AT_STRIDE + cc * 8) * 2;
        cp16(so, g_qf + gbase + (size_t)(qt * 64 + row) * DK_ + cc * 8);
    }
    at_load_kv(sb, 0, gbase, 0, tid);

    float oAcc[8][4];
#pragma unroll
    for (int nt = 0; nt < 8; ++nt)
#pragma unroll
        for (int c = 0; c < 4; ++c) oAcc[nt][c] = 0.0f;

    float m0 = -1e30f, m1 = -1e30f, l0 = 0.0f, l1 = 0.0f;
    const int row0g = qt * 64 + warp * 16 + (lane >> 2);

    uint32_t qf[4][4];
    bool qloaded = false;

#pragma unroll 1
    for (int kt = 0; kt <= qt; ++kt) {
        const int s = kt & 1;
        asm volatile("cp.async.wait_group 0;\n" ::);
        __syncthreads();
        if (kt + 1 <= qt)
            at_load_kv(sb, s ^ 1, gbase, kt + 1, tid);

        if (!qloaded) {
            qloaded = true;
#pragma unroll
            for (int k16 = 0; k16 < 4; ++k16) {
                int row = warp * 16 + (lane & 15);
                uint32_t off = (uint32_t)(row * AT_STRIDE + (lane >> 4) * 8 + k16 * 16) * 2;
                ldsm4(qf[k16], sb + off);
            }
        }

        const uint32_t kvb = sb + (AT_KVBASE + s * AT_STAGE) * 2;

        // ---- S = Q @ K^T (flattened, depth-2 K-frag prefetch) ----
        float sAcc[8][4];
#pragma unroll
        for (int nt = 0; nt < 8; ++nt)
#pragma unroll
            for (int c = 0; c < 4; ++c) sAcc[nt][c] = 0.0f;

        const int krow0 = (lane & 7) + ((lane >> 4) << 3);
        const uint32_t kcol = ((lane >> 3) & 1) * 8;
        auto kaddr = [&](int it) -> uint32_t {
            const int k16 = it >> 2, np = it & 3;
            return kvb + (uint32_t)((np * 16 + krow0) * AT_STRIDE + kcol + k16 * 16) * 2;
        };
        {
            uint32_t kfb[3][4];
            ldsm4(kfb[0], kaddr(0));
            ldsm4(kfb[1], kaddr(1));
#pragma unroll
            for (int it = 0; it < 16; ++it) {
                if (it + 2 < 16) ldsm4(kfb[(it + 2) % 3], kaddr(it + 2));
                const int k16 = it >> 2, np = it & 3;
                const uint32_t* kf = kfb[it % 3];
                mma16816f(sAcc[np * 2],     qf[k16], kf);
                mma16816f(sAcc[np * 2 + 1], qf[k16], kf + 2);
            }
        }

        // ---- scale + causal mask ----
        const float invs = 0.125f;
        if (kt == qt) {
#pragma unroll
            for (int nt = 0; nt < 8; ++nt) {
                const int colb = kt * 64 + nt * 8 + (lane & 3) * 2;
#pragma unroll
                for (int c = 0; c < 4; ++c) {
                    const int col = colb + (c & 1);
                    const int row = row0g + ((c >> 1) << 3);
                    sAcc[nt][c] = (col <= row) ? sAcc[nt][c] * invs : -1e30f;
                }
            }
        } else {
#pragma unroll
            for (int nt = 0; nt < 8; ++nt)
#pragma unroll
                for (int c = 0; c < 4; ++c) sAcc[nt][c] *= invs;
        }

        // ---- online softmax ----
        float mx0 = -1e30f, mx1 = -1e30f;
#pragma unroll
        for (int nt = 0; nt < 8; ++nt) {
            mx0 = fmaxf(mx0, fmaxf(sAcc[nt][0], sAcc[nt][1]));
            mx1 = fmaxf(mx1, fmaxf(sAcc[nt][2], sAcc[nt][3]));
        }
        mx0 = fmaxf(mx0, __shfl_xor_sync(0xffffffffu, mx0, 1));
        mx0 = fmaxf(mx0, __shfl_xor_sync(0xffffffffu, mx0, 2));
        mx1 = fmaxf(mx1, __shfl_xor_sync(0xffffffffu, mx1, 1));
        mx1 = fmaxf(mx1, __shfl_xor_sync(0xffffffffu, mx1, 2));

        const float mn0 = fmaxf(m0, mx0);
        const float mn1 = fmaxf(m1, mx1);
        const float fac0 = fexp(m0 - mn0);
        const float fac1 = fexp(m1 - mn1);
        m0 = mn0; m1 = mn1;

        float sum0 = 0.0f, sum1 = 0.0f;
#pragma unroll
        for (int nt = 0; nt < 8; ++nt) {
            sAcc[nt][0] = fexp(sAcc[nt][0] - m0);
            sAcc[nt][1] = fexp(sAcc[nt][1] - m0);
            sAcc[nt][2] = fexp(sAcc[nt][2] - m1);
            sAcc[nt][3] = fexp(sAcc[nt][3] - m1);
            sum0 += sAcc[nt][0] + sAcc[nt][1];
            sum1 += sAcc[nt][2] + sAcc[nt][3];
        }
        sum0 += __shfl_xor_sync(0xffffffffu, sum0, 1);
        sum0 += __shfl_xor_sync(0xffffffffu, sum0, 2);
        sum1 += __shfl_xor_sync(0xffffffffu, sum1, 1);
        sum1 += __shfl_xor_sync(0xffffffffu, sum1, 2);
        l0 = l0 * fac0 + sum0;
        l1 = l1 * fac1 + sum1;

#pragma unroll
        for (int nt = 0; nt < 8; ++nt) {
            oAcc[nt][0] *= fac0; oAcc[nt][1] *= fac0;
            oAcc[nt][2] *= fac1; oAcc[nt][3] *= fac1;
        }

        // ---- O += P @ V (flattened, depth-2 V-frag prefetch) ----
        const uint32_t vb = kvb + AT_TILE * 2;
        const int vrow0 = (lane & 7) + 8 * ((lane >> 3) & 1);
        const int vcol0 = 8 * (lane >> 4);
        auto vaddr = [&](int it) -> uint32_t {
            const int c16 = it >> 2, np = it & 3;
            return vb + (uint32_t)((c16 * 16 + vrow0) * AT_STRIDE + np * 16 + vcol0) * 2;
        };
        {
            uint32_t vfb[3][4];
            uint32_t pa[4];
            ldsm4t(vfb[0], vaddr(0));
            ldsm4t(vfb[1], vaddr(1));
#pragma unroll
            for (int it = 0; it < 16; ++it) {
                if (it + 2 < 16) ldsm4t(vfb[(it + 2) % 3], vaddr(it + 2));
                const int c16 = it >> 2, np = it & 3;
                if (np == 0) {
#pragma unroll
                    for (int half = 0; half < 2; ++half) {
                        const float* pv = sAcc[2 * c16 + half];
                        __half2 p01 = __floats2half2_rn(pv[0], pv[1]);
                        __half2 p23 = __floats2half2_rn(pv[2], pv[3]);
                        pa[half * 2 + 0] = *(uint32_t*)&p01;
                        pa[half * 2 + 1] = *(uint32_t*)&p23;
                    }
                }
                const uint32_t* vf = vfb[it % 3];
                mma16816f(oAcc[np * 2],     pa, vf);
                mma16816f(oAcc[np * 2 + 1], pa, vf + 2);
            }
        }
    }

    // ---- epilogue ----
    const float inv0 = 1.0f / l0;
    const float inv1 = 1.0f / l1;
    const int b = bh >> 4;
    const int h = bh & 15;
#pragma unroll
    for (int rr = 0; rr < 2; ++rr) {
        const int t = qt * 64 + warp * 16 + (lane >> 2) + rr * 8;
        const float inv = rr ? inv1 : inv0;
        size_t rowoff = AOFF + ((size_t)b * T_ + t) * D_ + h * DK_ + (lane & 3) * 2;
#pragma unroll
        for (int nt = 0; nt < 8; ++nt) {
            *(__half2*)&g_af[rowoff + nt * 8] = __floats2half2_rn(
                oAcc[nt][rr * 2] * inv, oAcc[nt][rr * 2 + 1] * inv);
        }
    }
}

// ---------------------------------------------------------------------------
// Launch
// ---------------------------------------------------------------------------
extern "C" void kernel_launch(void* const* d_in, const int* in_sizes, int n_in,
                              void* d_out, int out_size)
{
    (void)in_sizes; (void)n_in; (void)out_size;
    const float* x  = (const float*)d_in[0];
    const float* Wq = (const float*)d_in[2];
    const float* Wk = (const float*)d_in[3];
    const float* Wv = (const float*)d_in[4];
    const float* Wo = (const float*)d_in[5];
    const float* bq = (const float*)d_in[6];
    const float* bk = (const float*)d_in[7];
    const float* bv = (const float*)d_in[8];
    const float* bo = (const float*)d_in[9];
    float* out = (float*)d_out;

    conv_all<<<NBX + 4 * NBW, 256>>>(x, Wq, Wk, Wv, Wo);

    const int gemm_smem = G_NSTG * STAGE_B;   // 73728
    cudaFuncSetAttribute(mma_gemm<1>, cudaFuncAttributeMaxDynamicSharedMemorySize, gemm_smem);
    cudaFuncSetAttribute(mma_gemm<0>, cudaFuncAttributeMaxDynamicSharedMemorySize, gemm_smem);
    cudaFuncSetAttribute(attn_kernel, cudaFuncAttributeMaxDynamicSharedMemorySize, AT_SMEM_BYTES);

    // Fused QKV projection: grid (3*8, 64)
    mma_gemm<1><<<dim3(24, M_ / 128), 256, gemm_smem>>>(bq, bk, bv, nullptr);

    // Attention: 64 query rows per CTA, 2 CTAs/SM
    attn_kernel<<<dim3(T_ / 64, B_ * H_), 128, AT_SMEM_BYTES>>>();

    // Output projection
    mma_gemm<0><<<dim3(N_ / 128, M_ / 128), 256, gemm_smem>>>(bo, nullptr, nullptr, out);
}